// round 5
// baseline (speedup 1.0000x reference)
#include <cuda_runtime.h>

#define NN 50000
#define NE 100000
#define NODE_IN 64
#define EDGE_IN 16
#define H 32
#define EH 128
#define NTN 343
#define NTE 21
#define STEPS 6
#define NBLK ((NE + 255) / 256)   // 391
#define GRID_BLKS 296             // 2 blocks/SM x 148 SMs (GB300 has 152: all resident)
#define FULLM 0xffffffffu

// ---------------- device scratch ----------------
__device__ float d_h[NN * H];
__device__ float d_agg[NN * H];
__device__ float d_Wtab[NTE * H * H];
__device__ int d_ssrc[NE];
__device__ int d_sdst[NE];
__device__ int d_stype[NE];
__device__ int d_blkcnt[NBLK * NTE];
__device__ volatile int d_bar[32];

// ---------------- helpers ----------------
__device__ __forceinline__ unsigned long long pk(float a, float b) {
    unsigned long long r;
    asm("mov.b64 %0, {%1, %2};" : "=l"(r) : "f"(a), "f"(b));
    return r;
}
__device__ __forceinline__ float2 upk(unsigned long long v) {
    float2 f;
    asm("mov.b64 {%0, %1}, %2;" : "=f"(f.x), "=f"(f.y) : "l"(v));
    return f;
}
__device__ __forceinline__ void ffma2(unsigned long long& acc,
                                      unsigned long long a,
                                      unsigned long long b) {
    asm("fma.rn.f32x2 %0, %1, %2, %0;" : "+l"(acc) : "l"(a), "l"(b));
}
__device__ __forceinline__ float sigm(float x) {
    return 1.0f / (1.0f + __expf(-x));
}
__device__ __forceinline__ float tanh_fast(float x) {
    float e = __expf(2.0f * x);
    return 1.0f - 2.0f / (e + 1.0f);
}

// grid-wide barrier: unique slot per use, counters zeroed in setup each call
__device__ __forceinline__ void gridbar(int slot) {
    __threadfence();   // release stores + L1 invalidate (gpu-scope -> CCTL.IVALL)
    __syncthreads();
    if (threadIdx.x == 0) {
        atomicAdd((int*)&d_bar[slot], 1);
        while (d_bar[slot] < GRID_BLKS) { __nanosleep(64); }
        __threadfence();
    }
    __syncthreads();
}

// ---------------- launch 0: blockwise type histogram (+ zero barriers) -----
__global__ void k_count(const int* __restrict__ eid) {
    __shared__ int hc[NTE];
    if (threadIdx.x < NTE) hc[threadIdx.x] = 0;
    __syncthreads();
    int e = blockIdx.x * blockDim.x + threadIdx.x;
    if (e < NE) atomicAdd(&hc[eid[e]], 1);
    if (blockIdx.x == 0 && threadIdx.x < 32) d_bar[threadIdx.x] = 0;
    __syncthreads();
    if (threadIdx.x < NTE)
        d_blkcnt[blockIdx.x * NTE + threadIdx.x] = hc[threadIdx.x];
}

// ---------------- launch 1: type-sort scatter (fused global prefix) --------
__global__ void k_scatter(const int* __restrict__ eid,
                          const int* __restrict__ src,
                          const int* __restrict__ dst) {
    __shared__ int hc[NTE];
    __shared__ int hbase[NTE];
    __shared__ int htot[NTE];
    int b = blockIdx.x;
    if (threadIdx.x < NTE) hc[threadIdx.x] = 0;
    __syncthreads();
    int e = b * blockDim.x + threadIdx.x;
    int t = 0, loc = 0;
    bool valid = (e < NE);
    if (valid) {
        t = eid[e];
        loc = atomicAdd(&hc[t], 1);
    }
    __syncthreads();
    if (threadIdx.x < NTE) {
        int tt = threadIdx.x, before = 0, total = 0;
        for (int bb = 0; bb < NBLK; bb++) {
            int c = d_blkcnt[bb * NTE + tt];
            total += c;
            if (bb < b) before += c;
        }
        hbase[tt] = before;
        htot[tt] = total;
    }
    __syncthreads();
    if (threadIdx.x == 0) {
        int run = 0;
        for (int tt = 0; tt < NTE; tt++) {
            hbase[tt] += run;
            run += htot[tt];
        }
    }
    __syncthreads();
    if (valid) {
        int p = hbase[t] + loc;
        d_ssrc[p] = src[e];
        d_sdst[p] = dst[e];
        d_stype[p] = t;
    }
}

// ---------------- launch 2: wtab (blocks 0..20) + init h/agg (rest) --------
__global__ void __launch_bounds__(1024) k_wtab_init(
    const float* __restrict__ edge_emb, const float* __restrict__ eW1,
    const float* __restrict__ eb1, const float* __restrict__ eW2,
    const float* __restrict__ eb2, const int* __restrict__ node_ids,
    const float* __restrict__ node_emb, const float* __restrict__ proj_W,
    const float* __restrict__ proj_b) {
    int tid = threadIdx.x;
    if (blockIdx.x < NTE) {
        int t = blockIdx.x;
        __shared__ float sh[EH];
        if (tid < EH) {
            float a = eb1[tid];
#pragma unroll
            for (int i = 0; i < EDGE_IN; i++)
                a = fmaf(edge_emb[t * EDGE_IN + i], eW1[i * EH + tid], a);
            sh[tid] = fmaxf(a, 0.0f);
        }
        __syncthreads();
        float acc = eb2[tid];
#pragma unroll 8
        for (int i = 0; i < EH; i++)
            acc = fmaf(sh[i], eW2[i * (H * H) + tid], acc);
        d_Wtab[t * (H * H) + tid] = acc;
    } else {
        int idx = (blockIdx.x - NTE) * 1024 + tid;
        if (idx < NN * H) {
            int n = idx >> 5, o = idx & 31;
            int nid = node_ids[n];
            float acc = proj_b[o];
#pragma unroll 8
            for (int i = 0; i < NODE_IN; i++)
                acc = fmaf(node_emb[nid * NODE_IN + i], proj_W[i * H + o], acc);
            d_h[idx] = fmaxf(acc, 0.0f);
            d_agg[idx] = 0.0f;
        }
    }
}

// ---------------- launch 3: PERSISTENT 6-step loop -------------------------
// smem union: msg phase uses sbuf as hs[8][32][32] staging;
//             gru phase uses sbuf[0..6143] as sWih|sWhh (reloaded per phase).
__global__ void __launch_bounds__(256, 2) k_loop(
    const float* __restrict__ gWih, const float* __restrict__ gWhh,
    const float* __restrict__ gbih, const float* __restrict__ gbhh,
    const float* __restrict__ cb, float* __restrict__ outp) {
    __shared__ __align__(16) float sbuf[8192];  // 32 KB
    __shared__ float sbih[3 * H], sbhh[3 * H], scb[H];

    int tid = threadIdx.x;
    int wid = tid >> 5, lane = tid & 31;

    if (tid < 3 * H) {
        sbih[tid] = gbih[tid];
        sbhh[tid] = gbhh[tid];
    }
    if (tid < H) scb[tid] = cb[tid];

    const int NW = GRID_BLKS * 8;     // 2368 warps
    const int NCH = NE / 32;          // 3125 chunks (exact)
    int slot = 0;

    for (int s = 0; s < STEPS; s++) {
        // ======== message phase ========
        float(*hs)[32] = (float(*)[32])(sbuf + wid * 32 * 32);
        for (int gw = blockIdx.x * 8 + wid; gw < NCH; gw += NW) {
            int base = gw * 32;
            int e = base + lane;
            int sI = __ldg(&d_ssrc[e]);
            int dI = __ldg(&d_sdst[e]);
            int tI = __ldg(&d_stype[e]);

#pragma unroll 4
            for (int j = 0; j < 32; j++) {
                int sj = __shfl_sync(FULLM, sI, j);
                hs[j][lane] = __ldcg(&d_h[sj * H + lane]);
            }

            int cur_t = __shfl_sync(FULLM, tI, 0);
            unsigned long long w2[H / 2];
            {
                const float* Wt = d_Wtab + cur_t * (H * H);
#pragma unroll
                for (int q = 0; q < H / 2; q++)
                    w2[q] = pk(Wt[(2 * q) * H + lane], Wt[(2 * q + 1) * H + lane]);
            }
            __syncwarp();

#pragma unroll 2
            for (int j = 0; j < 32; j++) {
                int tj = __shfl_sync(FULLM, tI, j);
                if (tj != cur_t) {
                    cur_t = tj;
                    const float* Wt = d_Wtab + cur_t * (H * H);
#pragma unroll
                    for (int q = 0; q < H / 2; q++)
                        w2[q] = pk(Wt[(2 * q) * H + lane],
                                   Wt[(2 * q + 1) * H + lane]);
                }
                const ulonglong2* hp = (const ulonglong2*)hs[j];
                unsigned long long acc = 0;
#pragma unroll
                for (int p = 0; p < 8; p++) {
                    ulonglong2 hh = hp[p];
                    ffma2(acc, hh.x, w2[2 * p]);
                    ffma2(acc, hh.y, w2[2 * p + 1]);
                }
                float2 f = upk(acc);
                int dj = __shfl_sync(FULLM, dI, j);
                atomicAdd(&d_agg[dj * H + lane], f.x + f.y);
            }
            __syncwarp();
        }
        gridbar(slot++);

        // ======== GRU phase ========
        float* sWih = sbuf;
        float* sWhh = sbuf + 3 * H * H;
        for (int i = tid; i < 3 * H * H; i += 256) {
            sWih[i] = gWih[i];
            sWhh[i] = gWhh[i];
        }
        __syncthreads();

        int n = blockIdx.x * 256 + tid;
        if (n < NN) {
            unsigned long long m2[H / 2], h2[H / 2];
            {
                const float4* ag4 = (const float4*)(d_agg + (size_t)n * H);
                float4* agw = (float4*)(d_agg + (size_t)n * H);
                const float4* hh4 = (const float4*)(d_h + (size_t)n * H);
                float4 z4 = make_float4(0.f, 0.f, 0.f, 0.f);
#pragma unroll
                for (int q = 0; q < H / 4; q++) {
                    float4 a = __ldcg(ag4 + q);
                    float b0 = fmaxf(a.x + scb[q * 4 + 0], 0.f);
                    float b1 = fmaxf(a.y + scb[q * 4 + 1], 0.f);
                    float b2 = fmaxf(a.z + scb[q * 4 + 2], 0.f);
                    float b3 = fmaxf(a.w + scb[q * 4 + 3], 0.f);
                    m2[2 * q + 0] = pk(b0, b1);
                    m2[2 * q + 1] = pk(b2, b3);
                    agw[q] = z4;  // reset agg for next step
                    float4 hh = hh4[q];
                    h2[2 * q + 0] = pk(hh.x, hh.y);
                    h2[2 * q + 1] = pk(hh.z, hh.w);
                }
            }
#pragma unroll 1
            for (int o = 0; o < H; o++) {
                const ulonglong2* Wr = (const ulonglong2*)(sWih + o * H);
                const ulonglong2* Wz = (const ulonglong2*)(sWih + (H + o) * H);
                const ulonglong2* Wn = (const ulonglong2*)(sWih + (2 * H + o) * H);
                const ulonglong2* Vr = (const ulonglong2*)(sWhh + o * H);
                const ulonglong2* Vz = (const ulonglong2*)(sWhh + (H + o) * H);
                const ulonglong2* Vn = (const ulonglong2*)(sWhh + (2 * H + o) * H);
                unsigned long long air = 0, aiz = 0, ain = 0, ahr = 0, ahz = 0,
                                   ahn = 0;
#pragma unroll
                for (int p = 0; p < H / 4; p++) {
                    ulonglong2 w;
                    w = Wr[p]; ffma2(air, m2[2 * p], w.x); ffma2(air, m2[2 * p + 1], w.y);
                    w = Wz[p]; ffma2(aiz, m2[2 * p], w.x); ffma2(aiz, m2[2 * p + 1], w.y);
                    w = Wn[p]; ffma2(ain, m2[2 * p], w.x); ffma2(ain, m2[2 * p + 1], w.y);
                    w = Vr[p]; ffma2(ahr, h2[2 * p], w.x); ffma2(ahr, h2[2 * p + 1], w.y);
                    w = Vz[p]; ffma2(ahz, h2[2 * p], w.x); ffma2(ahz, h2[2 * p + 1], w.y);
                    w = Vn[p]; ffma2(ahn, h2[2 * p], w.x); ffma2(ahn, h2[2 * p + 1], w.y);
                }
                float2 f;
                f = upk(air); float ir = f.x + f.y + sbih[o];
                f = upk(aiz); float iz = f.x + f.y + sbih[H + o];
                f = upk(ain); float in_ = f.x + f.y + sbih[2 * H + o];
                f = upk(ahr); float hr = f.x + f.y + sbhh[o];
                f = upk(ahz); float hz = f.x + f.y + sbhh[H + o];
                f = upk(ahn); float hn = f.x + f.y + sbhh[2 * H + o];

                float r = sigm(ir + hr);
                float z = sigm(iz + hz);
                float nnv = tanh_fast(in_ + r * hn);
                float2 hp2 = upk(h2[o >> 1]);
                float hdo = (o & 1) ? hp2.y : hp2.x;
                float hnew = (1.0f - z) * nnv + z * hdo;
                d_h[(size_t)n * H + o] = hnew;
                if (s == STEPS - 1) outp[(size_t)n * H + o] = hnew;
            }
        }
        if (s != STEPS - 1) gridbar(slot++);
    }
}

// ---------------- launch ----------------
extern "C" void kernel_launch(void* const* d_in, const int* in_sizes, int n_in,
                              void* d_out, int out_size) {
    const int* node_ids = (const int*)d_in[0];
    const int* edge_ids = (const int*)d_in[1];
    const int* src = (const int*)d_in[2];
    const int* dst = (const int*)d_in[3];
    const float* node_emb = (const float*)d_in[4];
    const float* edge_emb = (const float*)d_in[5];
    const float* proj_W = (const float*)d_in[6];
    const float* proj_b = (const float*)d_in[7];
    const float* eW1 = (const float*)d_in[8];
    const float* eb1 = (const float*)d_in[9];
    const float* eW2 = (const float*)d_in[10];
    const float* eb2 = (const float*)d_in[11];
    const float* conv_bias = (const float*)d_in[12];
    const float* gWih = (const float*)d_in[13];
    const float* gWhh = (const float*)d_in[14];
    const float* gbih = (const float*)d_in[15];
    const float* gbhh = (const float*)d_in[16];
    float* out = (float*)d_out;

    k_count<<<NBLK, 256>>>(edge_ids);
    k_scatter<<<NBLK, 256>>>(edge_ids, src, dst);
    k_wtab_init<<<NTE + (NN * H + 1023) / 1024, 1024>>>(
        edge_emb, eW1, eb1, eW2, eb2, node_ids, node_emb, proj_W, proj_b);
    k_loop<<<GRID_BLKS, 256>>>(gWih, gWhh, gbih, gbhh, conv_bias, out);
}

// round 6
// speedup vs baseline: 1.2458x; 1.2458x over previous
#include <cuda_runtime.h>

#define NN 50000
#define NE 100000
#define NODE_IN 64
#define EDGE_IN 16
#define H 32
#define EH 128
#define NTN 343
#define NTE 21
#define STEPS 6
#define NBLK ((NE + 255) / 256)   // 391
#define FULLM 0xffffffffu

// ---------------- device scratch ----------------
__device__ float d_h[NN * H];
__device__ float d_agg[NN * H];
__device__ float d_Wtab[NTE * H * H];
__device__ int d_ssrc[NE];
__device__ int d_sdst[NE];
__device__ int d_stype[NE];
__device__ int d_blkcnt[NBLK * NTE];

// ---------------- helpers ----------------
__device__ __forceinline__ unsigned long long pk(float a, float b) {
    unsigned long long r;
    asm("mov.b64 %0, {%1, %2};" : "=l"(r) : "f"(a), "f"(b));
    return r;
}
__device__ __forceinline__ float2 upk(unsigned long long v) {
    float2 f;
    asm("mov.b64 {%0, %1}, %2;" : "=f"(f.x), "=f"(f.y) : "l"(v));
    return f;
}
__device__ __forceinline__ void ffma2(unsigned long long& acc,
                                      unsigned long long a,
                                      unsigned long long b) {
    asm("fma.rn.f32x2 %0, %1, %2, %0;" : "+l"(acc) : "l"(a), "l"(b));
}
__device__ __forceinline__ float sigm(float x) {
    return 1.0f / (1.0f + __expf(-x));
}
__device__ __forceinline__ float tanh_fast(float x) {
    float e = __expf(2.0f * x);
    return 1.0f - 2.0f / (e + 1.0f);
}
__device__ __forceinline__ unsigned smem_u32(const void* p) {
    unsigned a;
    asm("{ .reg .u64 t; cvta.to.shared.u64 t, %1; cvt.u32.u64 %0, t; }"
        : "=r"(a) : "l"(p));
    return a;
}

// ---------------- launch 0: blockwise type histogram ------------------------
__global__ void k_count(const int* __restrict__ eid) {
    __shared__ int hc[NTE];
    if (threadIdx.x < NTE) hc[threadIdx.x] = 0;
    __syncthreads();
    int e = blockIdx.x * blockDim.x + threadIdx.x;
    if (e < NE) atomicAdd(&hc[eid[e]], 1);
    __syncthreads();
    if (threadIdx.x < NTE)
        d_blkcnt[blockIdx.x * NTE + threadIdx.x] = hc[threadIdx.x];
}

// ---------------- launch 1: type-sort scatter (fused global prefix) --------
__global__ void k_scatter(const int* __restrict__ eid,
                          const int* __restrict__ src,
                          const int* __restrict__ dst) {
    __shared__ int hc[NTE];
    __shared__ int hbase[NTE];
    __shared__ int htot[NTE];
    int b = blockIdx.x;
    if (threadIdx.x < NTE) hc[threadIdx.x] = 0;
    __syncthreads();
    int e = b * blockDim.x + threadIdx.x;
    int t = 0, loc = 0;
    bool valid = (e < NE);
    if (valid) {
        t = eid[e];
        loc = atomicAdd(&hc[t], 1);
    }
    __syncthreads();
    if (threadIdx.x < NTE) {
        int tt = threadIdx.x, before = 0, total = 0;
        for (int bb = 0; bb < NBLK; bb++) {
            int c = d_blkcnt[bb * NTE + tt];
            total += c;
            if (bb < b) before += c;
        }
        hbase[tt] = before;
        htot[tt] = total;
    }
    __syncthreads();
    if (threadIdx.x == 0) {
        int run = 0;
        for (int tt = 0; tt < NTE; tt++) {
            hbase[tt] += run;
            run += htot[tt];
        }
    }
    __syncthreads();
    if (valid) {
        int p = hbase[t] + loc;
        d_ssrc[p] = src[e];
        d_sdst[p] = dst[e];
        d_stype[p] = t;
    }
}

// ---------------- launch 2: wtab (blocks 0..20) + init h/agg (rest) --------
__global__ void __launch_bounds__(1024) k_wtab_init(
    const float* __restrict__ edge_emb, const float* __restrict__ eW1,
    const float* __restrict__ eb1, const float* __restrict__ eW2,
    const float* __restrict__ eb2, const int* __restrict__ node_ids,
    const float* __restrict__ node_emb, const float* __restrict__ proj_W,
    const float* __restrict__ proj_b) {
    int tid = threadIdx.x;
    if (blockIdx.x < NTE) {
        int t = blockIdx.x;
        __shared__ float sh[EH];
        if (tid < EH) {
            float a = eb1[tid];
#pragma unroll
            for (int i = 0; i < EDGE_IN; i++)
                a = fmaf(edge_emb[t * EDGE_IN + i], eW1[i * EH + tid], a);
            sh[tid] = fmaxf(a, 0.0f);
        }
        __syncthreads();
        float acc = eb2[tid];
#pragma unroll 8
        for (int i = 0; i < EH; i++)
            acc = fmaf(sh[i], eW2[i * (H * H) + tid], acc);
        d_Wtab[t * (H * H) + tid] = acc;
    } else {
        int idx = (blockIdx.x - NTE) * 1024 + tid;
        if (idx < NN * H) {
            int n = idx >> 5, o = idx & 31;
            int nid = node_ids[n];
            float acc = proj_b[o];
#pragma unroll 8
            for (int i = 0; i < NODE_IN; i++)
                acc = fmaf(node_emb[nid * NODE_IN + i], proj_W[i * H + o], acc);
            d_h[idx] = fmaxf(acc, 0.0f);
            d_agg[idx] = 0.0f;
        }
    }
}

// ---------------- launch 3 (PROFILED): message kernel ----------------------
// Warp per 32 type-sorted edges. h[src] rows staged via per-lane 4B cp.async
// (no register landing, single wait per chunk); W register-resident as
// packed f32x2 (load overlaps the async copies); per-edge 8 LDS.128
// broadcasts + 16 ffma2; 32-lane coalesced atomicAdd scatter.
#define MSG_TPB 256
#define MSG_WPB (MSG_TPB / 32)
#define MSG_NCH (NE / 32)                       // 3125 (exact)
#define MSG_BLOCKS ((MSG_NCH + MSG_WPB - 1) / MSG_WPB)

__global__ void __launch_bounds__(MSG_TPB) k_message() {
    __shared__ __align__(16) float hs[MSG_WPB][32][32];
    int wid = threadIdx.x >> 5;
    int lane = threadIdx.x & 31;
    int gw = blockIdx.x * MSG_WPB + wid;
    if (gw >= MSG_NCH) return;

    int e = gw * 32 + lane;
    int sI = __ldg(&d_ssrc[e]);
    int dI = __ldg(&d_sdst[e]);
    int tI = __ldg(&d_stype[e]);

    // async stage: 32 independent 4B copies per lane, zero register landing
    unsigned sbase = smem_u32(&hs[wid][0][lane]);
#pragma unroll
    for (int j = 0; j < 32; j++) {
        int sj = __shfl_sync(FULLM, sI, j);
        const float* gp = &d_h[sj * H + lane];
        asm volatile("cp.async.ca.shared.global [%0], [%1], 4;"
                     :: "r"(sbase + j * 32 * 4), "l"(gp));
    }
    asm volatile("cp.async.commit_group;");

    // W load overlaps the in-flight copies
    int cur_t = __shfl_sync(FULLM, tI, 0);
    unsigned long long w2[H / 2];
    {
        const float* Wt = d_Wtab + cur_t * (H * H);
#pragma unroll
        for (int q = 0; q < H / 2; q++)
            w2[q] = pk(Wt[(2 * q) * H + lane], Wt[(2 * q + 1) * H + lane]);
    }
    asm volatile("cp.async.wait_group 0;");
    __syncwarp();

#pragma unroll 2
    for (int j = 0; j < 32; j++) {
        int tj = __shfl_sync(FULLM, tI, j);
        if (tj != cur_t) {
            cur_t = tj;
            const float* Wt = d_Wtab + cur_t * (H * H);
#pragma unroll
            for (int q = 0; q < H / 2; q++)
                w2[q] = pk(Wt[(2 * q) * H + lane], Wt[(2 * q + 1) * H + lane]);
        }
        const ulonglong2* hp = (const ulonglong2*)hs[wid][j];
        unsigned long long acc = 0;
#pragma unroll
        for (int p = 0; p < 8; p++) {
            ulonglong2 hh = hp[p];
            ffma2(acc, hh.x, w2[2 * p]);
            ffma2(acc, hh.y, w2[2 * p + 1]);
        }
        float2 f = upk(acc);
        int dj = __shfl_sync(FULLM, dI, j);
        atomicAdd(&d_agg[dj * H + lane], f.x + f.y);
    }
}

// ---------------- GRU kernel ----------------
__global__ void __launch_bounds__(256) k_gru(
    const float* __restrict__ gWih, const float* __restrict__ gWhh,
    const float* __restrict__ gbih, const float* __restrict__ gbhh,
    const float* __restrict__ cb, float* __restrict__ outp) {
    __shared__ __align__(16) float sWih[3 * H * H];
    __shared__ __align__(16) float sWhh[3 * H * H];
    __shared__ float sbih[3 * H], sbhh[3 * H], scb[H];

    for (int i = threadIdx.x; i < 3 * H * H; i += blockDim.x) {
        sWih[i] = gWih[i];
        sWhh[i] = gWhh[i];
    }
    for (int i = threadIdx.x; i < 3 * H; i += blockDim.x) {
        sbih[i] = gbih[i];
        sbhh[i] = gbhh[i];
    }
    if (threadIdx.x < H) scb[threadIdx.x] = cb[threadIdx.x];
    __syncthreads();

    int n = blockIdx.x * blockDim.x + threadIdx.x;
    if (n >= NN) return;

    unsigned long long m2[H / 2], h2[H / 2];
    {
        const float4* ag4 = (const float4*)(d_agg + (size_t)n * H);
        float4* agw = (float4*)(d_agg + (size_t)n * H);
        const float4* hh4 = (const float4*)(d_h + (size_t)n * H);
        float4 z4 = make_float4(0.f, 0.f, 0.f, 0.f);
#pragma unroll
        for (int q = 0; q < H / 4; q++) {
            float4 a = ag4[q];
            float b0 = fmaxf(a.x + scb[q * 4 + 0], 0.f);
            float b1 = fmaxf(a.y + scb[q * 4 + 1], 0.f);
            float b2 = fmaxf(a.z + scb[q * 4 + 2], 0.f);
            float b3 = fmaxf(a.w + scb[q * 4 + 3], 0.f);
            m2[2 * q + 0] = pk(b0, b1);
            m2[2 * q + 1] = pk(b2, b3);
            agw[q] = z4;  // reset agg for next step
            float4 hh = hh4[q];
            h2[2 * q + 0] = pk(hh.x, hh.y);
            h2[2 * q + 1] = pk(hh.z, hh.w);
        }
    }

#pragma unroll 1
    for (int o = 0; o < H; o++) {
        const ulonglong2* Wr = (const ulonglong2*)(sWih + o * H);
        const ulonglong2* Wz = (const ulonglong2*)(sWih + (H + o) * H);
        const ulonglong2* Wn = (const ulonglong2*)(sWih + (2 * H + o) * H);
        const ulonglong2* Vr = (const ulonglong2*)(sWhh + o * H);
        const ulonglong2* Vz = (const ulonglong2*)(sWhh + (H + o) * H);
        const ulonglong2* Vn = (const ulonglong2*)(sWhh + (2 * H + o) * H);
        unsigned long long air = 0, aiz = 0, ain = 0, ahr = 0, ahz = 0, ahn = 0;
#pragma unroll
        for (int p = 0; p < H / 4; p++) {
            ulonglong2 w;
            w = Wr[p]; ffma2(air, m2[2 * p], w.x); ffma2(air, m2[2 * p + 1], w.y);
            w = Wz[p]; ffma2(aiz, m2[2 * p], w.x); ffma2(aiz, m2[2 * p + 1], w.y);
            w = Wn[p]; ffma2(ain, m2[2 * p], w.x); ffma2(ain, m2[2 * p + 1], w.y);
            w = Vr[p]; ffma2(ahr, h2[2 * p], w.x); ffma2(ahr, h2[2 * p + 1], w.y);
            w = Vz[p]; ffma2(ahz, h2[2 * p], w.x); ffma2(ahz, h2[2 * p + 1], w.y);
            w = Vn[p]; ffma2(ahn, h2[2 * p], w.x); ffma2(ahn, h2[2 * p + 1], w.y);
        }
        float2 f;
        f = upk(air); float ir = f.x + f.y + sbih[o];
        f = upk(aiz); float iz = f.x + f.y + sbih[H + o];
        f = upk(ain); float in_ = f.x + f.y + sbih[2 * H + o];
        f = upk(ahr); float hr = f.x + f.y + sbhh[o];
        f = upk(ahz); float hz = f.x + f.y + sbhh[H + o];
        f = upk(ahn); float hn = f.x + f.y + sbhh[2 * H + o];

        float r = sigm(ir + hr);
        float z = sigm(iz + hz);
        float nnv = tanh_fast(in_ + r * hn);
        float2 hp2 = upk(h2[o >> 1]);
        float hdo = (o & 1) ? hp2.y : hp2.x;
        float hnew = (1.0f - z) * nnv + z * hdo;
        d_h[(size_t)n * H + o] = hnew;
        if (outp) outp[(size_t)n * H + o] = hnew;
    }
}

// ---------------- launch ----------------
extern "C" void kernel_launch(void* const* d_in, const int* in_sizes, int n_in,
                              void* d_out, int out_size) {
    const int* node_ids = (const int*)d_in[0];
    const int* edge_ids = (const int*)d_in[1];
    const int* src = (const int*)d_in[2];
    const int* dst = (const int*)d_in[3];
    const float* node_emb = (const float*)d_in[4];
    const float* edge_emb = (const float*)d_in[5];
    const float* proj_W = (const float*)d_in[6];
    const float* proj_b = (const float*)d_in[7];
    const float* eW1 = (const float*)d_in[8];
    const float* eb1 = (const float*)d_in[9];
    const float* eW2 = (const float*)d_in[10];
    const float* eb2 = (const float*)d_in[11];
    const float* conv_bias = (const float*)d_in[12];
    const float* gWih = (const float*)d_in[13];
    const float* gWhh = (const float*)d_in[14];
    const float* gbih = (const float*)d_in[15];
    const float* gbhh = (const float*)d_in[16];
    float* out = (float*)d_out;

    k_count<<<NBLK, 256>>>(edge_ids);                                  // 0
    k_scatter<<<NBLK, 256>>>(edge_ids, src, dst);                      // 1
    k_wtab_init<<<NTE + (NN * H + 1023) / 1024, 1024>>>(               // 2
        edge_emb, eW1, eb1, eW2, eb2, node_ids, node_emb, proj_W, proj_b);

    for (int s = 0; s < STEPS; s++) {
        k_message<<<MSG_BLOCKS, MSG_TPB>>>();                          // 3 (profiled), 5, ...
        float* op = (s == STEPS - 1) ? out : nullptr;
        k_gru<<<(NN + 255) / 256, 256>>>(gWih, gWhh, gbih, gbhh, conv_bias, op);
    }
}

// round 7
// speedup vs baseline: 1.4757x; 1.1846x over previous
#include <cuda_runtime.h>

#define NN 50000
#define NE 100000
#define NODE_IN 64
#define EDGE_IN 16
#define H 32
#define EH 128
#define NTN 343
#define NTE 21
#define STEPS 6
#define FULLM 0xffffffffu

// setupA block partition (1024 threads each)
#define INIT_BLKS ((NN * H + 1023) / 1024)        // 1563
#define CNT_BLKS ((NE + 1023) / 1024)             // 98
#define SETUPA_BLKS (NTE + INIT_BLKS + CNT_BLKS)  // 1682

// ---------------- device scratch ----------------
__device__ float d_h[NN * H];
__device__ float d_agg[NN * H];
__device__ float d_Wtab[NTE * H * H];
__device__ int d_ssrc[NE];
__device__ int d_sdst[NE];
__device__ int d_stype[NE];
__device__ int d_blkcnt[CNT_BLKS * NTE];

// ---------------- helpers ----------------
__device__ __forceinline__ unsigned long long pk(float a, float b) {
    unsigned long long r;
    asm("mov.b64 %0, {%1, %2};" : "=l"(r) : "f"(a), "f"(b));
    return r;
}
__device__ __forceinline__ float2 upk(unsigned long long v) {
    float2 f;
    asm("mov.b64 {%0, %1}, %2;" : "=f"(f.x), "=f"(f.y) : "l"(v));
    return f;
}
__device__ __forceinline__ void ffma2(unsigned long long& acc,
                                      unsigned long long a,
                                      unsigned long long b) {
    asm("fma.rn.f32x2 %0, %1, %2, %0;" : "+l"(acc) : "l"(a), "l"(b));
}
__device__ __forceinline__ float sigm(float x) {
    return 1.0f / (1.0f + __expf(-x));
}
__device__ __forceinline__ float tanh_fast(float x) {
    float e = __expf(2.0f * x);
    return 1.0f - 2.0f / (e + 1.0f);
}
__device__ __forceinline__ unsigned smem_u32(const void* p) {
    unsigned a;
    asm("{ .reg .u64 t; cvta.to.shared.u64 t, %1; cvt.u32.u64 %0, t; }"
        : "=r"(a) : "l"(p));
    return a;
}

// ---------------- launch 0: fused setup A (wtab | init | count) ------------
__global__ void __launch_bounds__(1024) k_setupA(
    const float* __restrict__ edge_emb, const float* __restrict__ eW1,
    const float* __restrict__ eb1, const float* __restrict__ eW2,
    const float* __restrict__ eb2, const int* __restrict__ node_ids,
    const float* __restrict__ node_emb, const float* __restrict__ proj_W,
    const float* __restrict__ proj_b, const int* __restrict__ eid) {
    int tid = threadIdx.x;
    int b = blockIdx.x;
    if (b < NTE) {
        // edge-type weight table
        __shared__ float sh[EH];
        if (tid < EH) {
            float a = eb1[tid];
#pragma unroll
            for (int i = 0; i < EDGE_IN; i++)
                a = fmaf(edge_emb[b * EDGE_IN + i], eW1[i * EH + tid], a);
            sh[tid] = fmaxf(a, 0.0f);
        }
        __syncthreads();
        float acc = eb2[tid];
#pragma unroll 8
        for (int i = 0; i < EH; i++)
            acc = fmaf(sh[i], eW2[i * (H * H) + tid], acc);
        d_Wtab[b * (H * H) + tid] = acc;
    } else if (b < NTE + INIT_BLKS) {
        // h init (inline projection) + agg zero
        int idx = (b - NTE) * 1024 + tid;
        if (idx < NN * H) {
            int n = idx >> 5, o = idx & 31;
            int nid = node_ids[n];
            float acc = proj_b[o];
#pragma unroll 8
            for (int i = 0; i < NODE_IN; i++)
                acc = fmaf(node_emb[nid * NODE_IN + i], proj_W[i * H + o], acc);
            d_h[idx] = fmaxf(acc, 0.0f);
            d_agg[idx] = 0.0f;
        }
    } else {
        // blockwise type histogram
        __shared__ int hc[NTE];
        int cb = b - NTE - INIT_BLKS;
        if (tid < NTE) hc[tid] = 0;
        __syncthreads();
        int e = cb * 1024 + tid;
        if (e < NE) atomicAdd(&hc[eid[e]], 1);
        __syncthreads();
        if (tid < NTE) d_blkcnt[cb * NTE + tid] = hc[tid];
    }
}

// ---------------- launch 1: type-sort scatter (fused global prefix) --------
__global__ void __launch_bounds__(1024) k_scatter(const int* __restrict__ eid,
                                                  const int* __restrict__ src,
                                                  const int* __restrict__ dst) {
    __shared__ int hc[NTE];
    __shared__ int hbase[NTE];
    __shared__ int htot[NTE];
    int b = blockIdx.x;
    if (threadIdx.x < NTE) hc[threadIdx.x] = 0;
    __syncthreads();
    int e = b * 1024 + threadIdx.x;
    int t = 0, loc = 0;
    bool valid = (e < NE);
    if (valid) {
        t = eid[e];
        loc = atomicAdd(&hc[t], 1);
    }
    __syncthreads();
    if (threadIdx.x < NTE) {
        int tt = threadIdx.x, before = 0, total = 0;
        for (int bb = 0; bb < CNT_BLKS; bb++) {
            int c = d_blkcnt[bb * NTE + tt];
            total += c;
            if (bb < b) before += c;
        }
        hbase[tt] = before;
        htot[tt] = total;
    }
    __syncthreads();
    if (threadIdx.x == 0) {
        int run = 0;
        for (int tt = 0; tt < NTE; tt++) {
            hbase[tt] += run;
            run += htot[tt];
        }
    }
    __syncthreads();
    if (valid) {
        int p = hbase[t] + loc;
        d_ssrc[p] = src[e];
        d_sdst[p] = dst[e];
        d_stype[p] = t;
    }
}

// ---------------- launch 2 (even steps): message kernel --------------------
#define MSG_TPB 256
#define MSG_WPB (MSG_TPB / 32)
#define MSG_NCH (NE / 32)  // 3125 exact
#define MSG_BLOCKS ((MSG_NCH + MSG_WPB - 1) / MSG_WPB)

__global__ void __launch_bounds__(MSG_TPB) k_message() {
    __shared__ __align__(16) float hs[MSG_WPB][32][32];
    int wid = threadIdx.x >> 5;
    int lane = threadIdx.x & 31;
    int gw = blockIdx.x * MSG_WPB + wid;
    if (gw >= MSG_NCH) return;

    int e = gw * 32 + lane;
    int sI = __ldg(&d_ssrc[e]);
    int dI = __ldg(&d_sdst[e]);
    int tI = __ldg(&d_stype[e]);

    unsigned sbase = smem_u32(&hs[wid][0][lane]);
#pragma unroll
    for (int j = 0; j < 32; j++) {
        int sj = __shfl_sync(FULLM, sI, j);
        const float* gp = &d_h[sj * H + lane];
        asm volatile("cp.async.ca.shared.global [%0], [%1], 4;"
                     :: "r"(sbase + j * 32 * 4), "l"(gp));
    }
    asm volatile("cp.async.commit_group;");

    int cur_t = __shfl_sync(FULLM, tI, 0);
    unsigned long long w2[H / 2];
    {
        const float* Wt = d_Wtab + cur_t * (H * H);
#pragma unroll
        for (int q = 0; q < H / 2; q++)
            w2[q] = pk(Wt[(2 * q) * H + lane], Wt[(2 * q + 1) * H + lane]);
    }
    asm volatile("cp.async.wait_group 0;");
    __syncwarp();

#pragma unroll 2
    for (int j = 0; j < 32; j++) {
        int tj = __shfl_sync(FULLM, tI, j);
        if (tj != cur_t) {
            cur_t = tj;
            const float* Wt = d_Wtab + cur_t * (H * H);
#pragma unroll
            for (int q = 0; q < H / 2; q++)
                w2[q] = pk(Wt[(2 * q) * H + lane], Wt[(2 * q + 1) * H + lane]);
        }
        const ulonglong2* hp = (const ulonglong2*)hs[wid][j];
        unsigned long long acc = 0;
#pragma unroll
        for (int p = 0; p < 8; p++) {
            ulonglong2 hh = hp[p];
            ffma2(acc, hh.x, w2[2 * p]);
            ffma2(acc, hh.y, w2[2 * p + 1]);
        }
        float2 f = upk(acc);
        int dj = __shfl_sync(FULLM, dI, j);
        atomicAdd(&d_agg[dj * H + lane], f.x + f.y);
    }
}

// ---------------- launch 3 (PROFILED): GRU kernel --------------------------
// 128-thread blocks, 391 blocks -> all co-resident in ONE wave (<=4 blk/SM),
// no tail. Bias folded into accumulator init.
#define GRU_TPB 128
#define GRU_BLOCKS ((NN + GRU_TPB - 1) / GRU_TPB)  // 391

__global__ void __launch_bounds__(GRU_TPB) k_gru(
    const float* __restrict__ gWih, const float* __restrict__ gWhh,
    const float* __restrict__ gbih, const float* __restrict__ gbhh,
    const float* __restrict__ cb, float* __restrict__ outp) {
    __shared__ __align__(16) float sWih[3 * H * H];
    __shared__ __align__(16) float sWhh[3 * H * H];
    __shared__ float sbih[3 * H], sbhh[3 * H], scb[H];

    for (int i = threadIdx.x; i < 3 * H * H; i += GRU_TPB) {
        sWih[i] = gWih[i];
        sWhh[i] = gWhh[i];
    }
    if (threadIdx.x < 3 * H) {
        sbih[threadIdx.x] = gbih[threadIdx.x];
        sbhh[threadIdx.x] = gbhh[threadIdx.x];
    }
    if (threadIdx.x < H) scb[threadIdx.x] = cb[threadIdx.x];
    __syncthreads();

    int n = blockIdx.x * GRU_TPB + threadIdx.x;
    if (n >= NN) return;

    unsigned long long m2[H / 2], h2[H / 2];
    {
        const float4* ag4 = (const float4*)(d_agg + (size_t)n * H);
        float4* agw = (float4*)(d_agg + (size_t)n * H);
        const float4* hh4 = (const float4*)(d_h + (size_t)n * H);
        float4 z4 = make_float4(0.f, 0.f, 0.f, 0.f);
#pragma unroll
        for (int q = 0; q < H / 4; q++) {
            float4 a = ag4[q];
            float b0 = fmaxf(a.x + scb[q * 4 + 0], 0.f);
            float b1 = fmaxf(a.y + scb[q * 4 + 1], 0.f);
            float b2 = fmaxf(a.z + scb[q * 4 + 2], 0.f);
            float b3 = fmaxf(a.w + scb[q * 4 + 3], 0.f);
            m2[2 * q + 0] = pk(b0, b1);
            m2[2 * q + 1] = pk(b2, b3);
            agw[q] = z4;  // reset agg for next step
            float4 hh = hh4[q];
            h2[2 * q + 0] = pk(hh.x, hh.y);
            h2[2 * q + 1] = pk(hh.z, hh.w);
        }
    }

#pragma unroll 2
    for (int o = 0; o < H; o++) {
        const ulonglong2* Wr = (const ulonglong2*)(sWih + o * H);
        const ulonglong2* Wz = (const ulonglong2*)(sWih + (H + o) * H);
        const ulonglong2* Wn = (const ulonglong2*)(sWih + (2 * H + o) * H);
        const ulonglong2* Vr = (const ulonglong2*)(sWhh + o * H);
        const ulonglong2* Vz = (const ulonglong2*)(sWhh + (H + o) * H);
        const ulonglong2* Vn = (const ulonglong2*)(sWhh + (2 * H + o) * H);
        // bias folded into lane0 of accumulators
        unsigned long long air = pk(sbih[o], 0.f);
        unsigned long long aiz = pk(sbih[H + o], 0.f);
        unsigned long long ain = pk(sbih[2 * H + o], 0.f);
        unsigned long long ahr = pk(sbhh[o], 0.f);
        unsigned long long ahz = pk(sbhh[H + o], 0.f);
        unsigned long long ahn = pk(sbhh[2 * H + o], 0.f);
#pragma unroll
        for (int p = 0; p < H / 4; p++) {
            ulonglong2 w;
            w = Wr[p]; ffma2(air, m2[2 * p], w.x); ffma2(air, m2[2 * p + 1], w.y);
            w = Wz[p]; ffma2(aiz, m2[2 * p], w.x); ffma2(aiz, m2[2 * p + 1], w.y);
            w = Wn[p]; ffma2(ain, m2[2 * p], w.x); ffma2(ain, m2[2 * p + 1], w.y);
            w = Vr[p]; ffma2(ahr, h2[2 * p], w.x); ffma2(ahr, h2[2 * p + 1], w.y);
            w = Vz[p]; ffma2(ahz, h2[2 * p], w.x); ffma2(ahz, h2[2 * p + 1], w.y);
            w = Vn[p]; ffma2(ahn, h2[2 * p], w.x); ffma2(ahn, h2[2 * p + 1], w.y);
        }
        float2 f, g;
        f = upk(air); g = upk(ahr);
        float r = sigm((f.x + f.y) + (g.x + g.y));
        f = upk(aiz); g = upk(ahz);
        float z = sigm((f.x + f.y) + (g.x + g.y));
        f = upk(ain); g = upk(ahn);
        float nnv = tanh_fast((f.x + f.y) + r * (g.x + g.y));
        float2 hp2 = upk(h2[o >> 1]);
        float hdo = (o & 1) ? hp2.y : hp2.x;
        float hnew = (1.0f - z) * nnv + z * hdo;
        d_h[(size_t)n * H + o] = hnew;
        if (outp) outp[(size_t)n * H + o] = hnew;
    }
}

// ---------------- launch ----------------
extern "C" void kernel_launch(void* const* d_in, const int* in_sizes, int n_in,
                              void* d_out, int out_size) {
    const int* node_ids = (const int*)d_in[0];
    const int* edge_ids = (const int*)d_in[1];
    const int* src = (const int*)d_in[2];
    const int* dst = (const int*)d_in[3];
    const float* node_emb = (const float*)d_in[4];
    const float* edge_emb = (const float*)d_in[5];
    const float* proj_W = (const float*)d_in[6];
    const float* proj_b = (const float*)d_in[7];
    const float* eW1 = (const float*)d_in[8];
    const float* eb1 = (const float*)d_in[9];
    const float* eW2 = (const float*)d_in[10];
    const float* eb2 = (const float*)d_in[11];
    const float* conv_bias = (const float*)d_in[12];
    const float* gWih = (const float*)d_in[13];
    const float* gWhh = (const float*)d_in[14];
    const float* gbih = (const float*)d_in[15];
    const float* gbhh = (const float*)d_in[16];
    float* out = (float*)d_out;

    k_setupA<<<SETUPA_BLKS, 1024>>>(edge_emb, eW1, eb1, eW2, eb2, node_ids,
                                    node_emb, proj_W, proj_b, edge_ids);  // 0
    k_scatter<<<CNT_BLKS, 1024>>>(edge_ids, src, dst);                    // 1

    for (int s = 0; s < STEPS; s++) {
        k_message<<<MSG_BLOCKS, MSG_TPB>>>();                             // 2, 4, ...
        float* op = (s == STEPS - 1) ? out : nullptr;
        k_gru<<<GRU_BLOCKS, GRU_TPB>>>(gWih, gWhh, gbih, gbhh,            // 3 (profiled)
                                       conv_bias, op);
    }
}

// round 8
// speedup vs baseline: 1.4782x; 1.0017x over previous
#include <cuda_runtime.h>

#define NN 50000
#define NE 100000
#define NODE_IN 64
#define EDGE_IN 16
#define H 32
#define EH 128
#define NTN 343
#define NTE 21
#define STEPS 6
#define FULLM 0xffffffffu

// setupA block partition (1024 threads each)
#define INIT_BLKS ((NN * H + 1023) / 1024)        // 1563
#define CNT_BLKS ((NE + 1023) / 1024)             // 98
#define SETUPA_BLKS (NTE + INIT_BLKS + CNT_BLKS)

// ---------------- device scratch ----------------
__device__ float d_h[NN * H];
__device__ float d_agg[NN * H];
__device__ float d_Wtab[NTE * H * H];
__device__ int d_ssrc[NE];
__device__ int d_sdst[NE];
__device__ int d_stype[NE];
__device__ int d_blkcnt[CNT_BLKS * NTE];

// ---------------- helpers ----------------
__device__ __forceinline__ unsigned long long pk(float a, float b) {
    unsigned long long r;
    asm("mov.b64 %0, {%1, %2};" : "=l"(r) : "f"(a), "f"(b));
    return r;
}
__device__ __forceinline__ float2 upk(unsigned long long v) {
    float2 f;
    asm("mov.b64 {%0, %1}, %2;" : "=f"(f.x), "=f"(f.y) : "l"(v));
    return f;
}
__device__ __forceinline__ void ffma2(unsigned long long& acc,
                                      unsigned long long a,
                                      unsigned long long b) {
    asm("fma.rn.f32x2 %0, %1, %2, %0;" : "+l"(acc) : "l"(a), "l"(b));
}
__device__ __forceinline__ float sigm(float x) {
    return 1.0f / (1.0f + __expf(-x));
}
__device__ __forceinline__ float tanh_fast(float x) {
    float e = __expf(2.0f * x);
    return 1.0f - 2.0f / (e + 1.0f);
}
__device__ __forceinline__ unsigned smem_u32(const void* p) {
    unsigned a;
    asm("{ .reg .u64 t; cvta.to.shared.u64 t, %1; cvt.u32.u64 %0, t; }"
        : "=r"(a) : "l"(p));
    return a;
}

// ---------------- launch 0: fused setup A (wtab | init | count) ------------
__global__ void __launch_bounds__(1024) k_setupA(
    const float* __restrict__ edge_emb, const float* __restrict__ eW1,
    const float* __restrict__ eb1, const float* __restrict__ eW2,
    const float* __restrict__ eb2, const int* __restrict__ node_ids,
    const float* __restrict__ node_emb, const float* __restrict__ proj_W,
    const float* __restrict__ proj_b, const int* __restrict__ eid) {
    int tid = threadIdx.x;
    int b = blockIdx.x;
    if (b < NTE) {
        __shared__ float sh[EH];
        if (tid < EH) {
            float a = eb1[tid];
#pragma unroll
            for (int i = 0; i < EDGE_IN; i++)
                a = fmaf(edge_emb[b * EDGE_IN + i], eW1[i * EH + tid], a);
            sh[tid] = fmaxf(a, 0.0f);
        }
        __syncthreads();
        float acc = eb2[tid];
#pragma unroll 8
        for (int i = 0; i < EH; i++)
            acc = fmaf(sh[i], eW2[i * (H * H) + tid], acc);
        d_Wtab[b * (H * H) + tid] = acc;
    } else if (b < NTE + INIT_BLKS) {
        int idx = (b - NTE) * 1024 + tid;
        if (idx < NN * H) {
            int n = idx >> 5, o = idx & 31;
            int nid = node_ids[n];
            float acc = proj_b[o];
#pragma unroll 8
            for (int i = 0; i < NODE_IN; i++)
                acc = fmaf(node_emb[nid * NODE_IN + i], proj_W[i * H + o], acc);
            d_h[idx] = fmaxf(acc, 0.0f);
            d_agg[idx] = 0.0f;
        }
    } else {
        __shared__ int hc[NTE];
        int cb2 = b - NTE - INIT_BLKS;
        if (tid < NTE) hc[tid] = 0;
        __syncthreads();
        int e = cb2 * 1024 + tid;
        if (e < NE) atomicAdd(&hc[eid[e]], 1);
        __syncthreads();
        if (tid < NTE) d_blkcnt[cb2 * NTE + tid] = hc[tid];
    }
}

// ---------------- launch 1: type-sort scatter (fused global prefix) --------
__global__ void __launch_bounds__(1024) k_scatter(const int* __restrict__ eid,
                                                  const int* __restrict__ src,
                                                  const int* __restrict__ dst) {
    __shared__ int hc[NTE];
    __shared__ int hbase[NTE];
    __shared__ int htot[NTE];
    int b = blockIdx.x;
    if (threadIdx.x < NTE) hc[threadIdx.x] = 0;
    __syncthreads();
    int e = b * 1024 + threadIdx.x;
    int t = 0, loc = 0;
    bool valid = (e < NE);
    if (valid) {
        t = eid[e];
        loc = atomicAdd(&hc[t], 1);
    }
    __syncthreads();
    if (threadIdx.x < NTE) {
        int tt = threadIdx.x, before = 0, total = 0;
        for (int bb = 0; bb < CNT_BLKS; bb++) {
            int c = d_blkcnt[bb * NTE + tt];
            total += c;
            if (bb < b) before += c;
        }
        hbase[tt] = before;
        htot[tt] = total;
    }
    __syncthreads();
    if (threadIdx.x == 0) {
        int run = 0;
        for (int tt = 0; tt < NTE; tt++) {
            hbase[tt] += run;
            run += htot[tt];
        }
    }
    __syncthreads();
    if (valid) {
        int p = hbase[t] + loc;
        d_ssrc[p] = src[e];
        d_sdst[p] = dst[e];
        d_stype[p] = t;
    }
}

// ---------------- launch 2 (even): message kernel --------------------------
#define MSG_TPB 256
#define MSG_WPB (MSG_TPB / 32)
#define MSG_NCH (NE / 32)
#define MSG_BLOCKS ((MSG_NCH + MSG_WPB - 1) / MSG_WPB)

__global__ void __launch_bounds__(MSG_TPB) k_message() {
    __shared__ __align__(16) float hs[MSG_WPB][32][32];
    int wid = threadIdx.x >> 5;
    int lane = threadIdx.x & 31;
    int gw = blockIdx.x * MSG_WPB + wid;
    if (gw >= MSG_NCH) return;

    int e = gw * 32 + lane;
    int sI = __ldg(&d_ssrc[e]);
    int dI = __ldg(&d_sdst[e]);
    int tI = __ldg(&d_stype[e]);

    unsigned sbase = smem_u32(&hs[wid][0][lane]);
#pragma unroll
    for (int j = 0; j < 32; j++) {
        int sj = __shfl_sync(FULLM, sI, j);
        const float* gp = &d_h[sj * H + lane];
        asm volatile("cp.async.ca.shared.global [%0], [%1], 4;"
                     :: "r"(sbase + j * 32 * 4), "l"(gp));
    }
    asm volatile("cp.async.commit_group;");

    int cur_t = __shfl_sync(FULLM, tI, 0);
    unsigned long long w2[H / 2];
    {
        const float* Wt = d_Wtab + cur_t * (H * H);
#pragma unroll
        for (int q = 0; q < H / 2; q++)
            w2[q] = pk(Wt[(2 * q) * H + lane], Wt[(2 * q + 1) * H + lane]);
    }
    asm volatile("cp.async.wait_group 0;");
    __syncwarp();

#pragma unroll 2
    for (int j = 0; j < 32; j++) {
        int tj = __shfl_sync(FULLM, tI, j);
        if (tj != cur_t) {
            cur_t = tj;
            const float* Wt = d_Wtab + cur_t * (H * H);
#pragma unroll
            for (int q = 0; q < H / 2; q++)
                w2[q] = pk(Wt[(2 * q) * H + lane], Wt[(2 * q + 1) * H + lane]);
        }
        const ulonglong2* hp = (const ulonglong2*)hs[wid][j];
        unsigned long long acc = 0;
#pragma unroll
        for (int p = 0; p < 8; p++) {
            ulonglong2 hh = hp[p];
            ffma2(acc, hh.x, w2[2 * p]);
            ffma2(acc, hh.y, w2[2 * p + 1]);
        }
        float2 f = upk(acc);
        int dj = __shfl_sync(FULLM, dI, j);
        atomicAdd(&d_agg[dj * H + lane], f.x + f.y);
    }
}

// ---------------- launch 3 (PROFILED): GRU v2 -------------------------------
// 6 warps/block; warp g owns gate g (ir,iz,in,hr,hz,hn); lane's weight row
// lives in 16 registers. Block processes 64 nodes (2 batches of 32):
// stage m/h in smem -> per node: 8 broadcast LDS.128 + 16 ffma2 + 1 STS ->
// combine phase applies the GRU nonlinearity and writes d_h.
#define G2_TPB 192
#define G2_NODES 64
#define G2_BLOCKS ((NN + G2_NODES - 1) / G2_NODES)  // 782

__global__ void __launch_bounds__(G2_TPB) k_gru2(
    const float* __restrict__ gWih, const float* __restrict__ gWhh,
    const float* __restrict__ gbih, const float* __restrict__ gbhh,
    const float* __restrict__ cb, float* __restrict__ outp) {
    __shared__ __align__(16) float sm_m[32 * 32];
    __shared__ __align__(16) float sm_h[32 * 32];
    __shared__ __align__(16) float sgate[6 * 32 * 32];

    int tid = threadIdx.x;
    int w = tid >> 5;    // 0..5 gate id
    int lane = tid & 31; // output index within gate

    // lane-private weight row (32 floats -> 16 packed regs), bias folded
    const float* Wsrc = (w < 3) ? gWih : gWhh;
    int row = (w < 3 ? w : w - 3) * 32 + lane;
    unsigned long long wreg[16];
    {
        const ulonglong2* wp = (const ulonglong2*)(Wsrc + row * H);
#pragma unroll
        for (int p = 0; p < 8; p++) {
            ulonglong2 v = __ldg(wp + p);
            wreg[2 * p] = v.x;
            wreg[2 * p + 1] = v.y;
        }
    }
    float bias = (w < 3) ? __ldg(gbih + row) : __ldg(gbhh + row);

    int nbase0 = blockIdx.x * G2_NODES;
#pragma unroll 1
    for (int half = 0; half < 2; half++) {
        int nbase = nbase0 + half * 32;

        // ---- stage m = relu(agg + cb), h; zero agg ----
        for (int idx = tid; idx < 1024; idx += G2_TPB) {
            int j = idx >> 5, o = idx & 31;
            int n = nbase + j;
            float mv = 0.f, hv = 0.f;
            if (n < NN) {
                size_t off = (size_t)n * H + o;
                float a = d_agg[off];
                mv = fmaxf(a + __ldg(cb + o), 0.f);
                d_agg[off] = 0.f;
                hv = d_h[off];
            }
            sm_m[idx] = mv;
            sm_h[idx] = hv;
        }
        __syncthreads();

        // ---- gemm: warp computes its gate for 32 nodes ----
        const float* srcbase = (w < 3) ? sm_m : sm_h;
#pragma unroll 4
        for (int j = 0; j < 32; j++) {
            const ulonglong2* sp = (const ulonglong2*)(srcbase + j * H);
            unsigned long long acc = pk(bias, 0.f);
#pragma unroll
            for (int p = 0; p < 8; p++) {
                ulonglong2 v = sp[p];  // broadcast LDS.128
                ffma2(acc, v.x, wreg[2 * p]);
                ffma2(acc, v.y, wreg[2 * p + 1]);
            }
            float2 f = upk(acc);
            sgate[w * 1024 + j * 32 + lane] = f.x + f.y;
        }
        __syncthreads();

        // ---- combine: GRU nonlinearity, write h ----
        for (int idx = tid; idx < 1024; idx += G2_TPB) {
            int n = nbase + (idx >> 5);
            if (n < NN) {
                float ir = sgate[idx];
                float iz = sgate[1024 + idx];
                float in_ = sgate[2048 + idx];
                float hr = sgate[3072 + idx];
                float hz = sgate[4096 + idx];
                float hn = sgate[5120 + idx];
                float r = sigm(ir + hr);
                float z = sigm(iz + hz);
                float nnv = tanh_fast(in_ + r * hn);
                float hold = sm_h[idx];
                float hnew = (1.0f - z) * nnv + z * hold;
                size_t off = (size_t)n * H + (idx & 31);
                d_h[off] = hnew;
                if (outp) outp[off] = hnew;
            }
        }
        __syncthreads();
    }
}

// ---------------- launch ----------------
extern "C" void kernel_launch(void* const* d_in, const int* in_sizes, int n_in,
                              void* d_out, int out_size) {
    const int* node_ids = (const int*)d_in[0];
    const int* edge_ids = (const int*)d_in[1];
    const int* src = (const int*)d_in[2];
    const int* dst = (const int*)d_in[3];
    const float* node_emb = (const float*)d_in[4];
    const float* edge_emb = (const float*)d_in[5];
    const float* proj_W = (const float*)d_in[6];
    const float* proj_b = (const float*)d_in[7];
    const float* eW1 = (const float*)d_in[8];
    const float* eb1 = (const float*)d_in[9];
    const float* eW2 = (const float*)d_in[10];
    const float* eb2 = (const float*)d_in[11];
    const float* conv_bias = (const float*)d_in[12];
    const float* gWih = (const float*)d_in[13];
    const float* gWhh = (const float*)d_in[14];
    const float* gbih = (const float*)d_in[15];
    const float* gbhh = (const float*)d_in[16];
    float* out = (float*)d_out;

    k_setupA<<<SETUPA_BLKS, 1024>>>(edge_emb, eW1, eb1, eW2, eb2, node_ids,
                                    node_emb, proj_W, proj_b, edge_ids);  // 0
    k_scatter<<<CNT_BLKS, 1024>>>(edge_ids, src, dst);                    // 1

    for (int s = 0; s < STEPS; s++) {
        k_message<<<MSG_BLOCKS, MSG_TPB>>>();                             // 2, 4, ...
        float* op = (s == STEPS - 1) ? out : nullptr;
        k_gru2<<<G2_BLOCKS, G2_TPB>>>(gWih, gWhh, gbih, gbhh,             // 3 (profiled)
                                      conv_bias, op);
    }
}

// round 9
// speedup vs baseline: 1.6023x; 1.0839x over previous
#include <cuda_runtime.h>

#define NN 50000
#define NE 100000
#define NODE_IN 64
#define EDGE_IN 16
#define H 32
#define EH 128
#define NTN 343
#define NTE 21
#define STEPS 6
#define FULLM 0xffffffffu

#define CNT_BLKS ((NE + 1023) / 1024)             // 98
#define HT_BLKS ((NTN * H + 1023) / 1024)         // 11
#define SETUPA_BLKS (NTE + HT_BLKS + CNT_BLKS)    // 130
#define INIT_BLKS ((NN * H + 1023) / 1024)        // 1563

// ---------------- device scratch ----------------
__device__ float d_h[NN * H];
__device__ float d_agg[NN * H];
__device__ float d_Wtab[NTE * H * H];
__device__ float d_htab[NTN * H];
__device__ int d_ssrc[NE];
__device__ int d_sdst[NE];
__device__ int d_stype[NE];
__device__ int d_blkcnt[CNT_BLKS * NTE];

// ---------------- helpers ----------------
__device__ __forceinline__ unsigned long long pk(float a, float b) {
    unsigned long long r;
    asm("mov.b64 %0, {%1, %2};" : "=l"(r) : "f"(a), "f"(b));
    return r;
}
__device__ __forceinline__ float2 upk(unsigned long long v) {
    float2 f;
    asm("mov.b64 {%0, %1}, %2;" : "=f"(f.x), "=f"(f.y) : "l"(v));
    return f;
}
__device__ __forceinline__ void ffma2(unsigned long long& acc,
                                      unsigned long long a,
                                      unsigned long long b) {
    asm("fma.rn.f32x2 %0, %1, %2, %0;" : "+l"(acc) : "l"(a), "l"(b));
}
__device__ __forceinline__ float sigm(float x) {
    return 1.0f / (1.0f + __expf(-x));
}
__device__ __forceinline__ float tanh_fast(float x) {
    float e = __expf(2.0f * x);
    return 1.0f - 2.0f / (e + 1.0f);
}
__device__ __forceinline__ unsigned smem_u32(const void* p) {
    unsigned a;
    asm("{ .reg .u64 t; cvta.to.shared.u64 t, %1; cvt.u32.u64 %0, t; }"
        : "=r"(a) : "l"(p));
    return a;
}

// ---------------- launch 0: setup A (wtab | htab | count) ------------------
__global__ void __launch_bounds__(1024) k_setupA(
    const float* __restrict__ edge_emb, const float* __restrict__ eW1,
    const float* __restrict__ eb1, const float* __restrict__ eW2,
    const float* __restrict__ eb2, const float* __restrict__ node_emb,
    const float* __restrict__ proj_W, const float* __restrict__ proj_b,
    const int* __restrict__ eid) {
    int tid = threadIdx.x;
    int b = blockIdx.x;
    if (b < NTE) {
        __shared__ float sh[EH];
        if (tid < EH) {
            float a = eb1[tid];
#pragma unroll
            for (int i = 0; i < EDGE_IN; i++)
                a = fmaf(edge_emb[b * EDGE_IN + i], eW1[i * EH + tid], a);
            sh[tid] = fmaxf(a, 0.0f);
        }
        __syncthreads();
        float acc = eb2[tid];
#pragma unroll 8
        for (int i = 0; i < EH; i++)
            acc = fmaf(sh[i], eW2[i * (H * H) + tid], acc);
        d_Wtab[b * (H * H) + tid] = acc;
    } else if (b < NTE + HT_BLKS) {
        // node projection table: 343 x 32
        int idx = (b - NTE) * 1024 + tid;
        if (idx < NTN * H) {
            int r = idx >> 5, o = idx & 31;
            float acc = proj_b[o];
#pragma unroll 8
            for (int i = 0; i < NODE_IN; i++)
                acc = fmaf(node_emb[r * NODE_IN + i], proj_W[i * H + o], acc);
            d_htab[idx] = fmaxf(acc, 0.0f);
        }
    } else {
        __shared__ int hc[NTE];
        int cb2 = b - NTE - HT_BLKS;
        if (tid < NTE) hc[tid] = 0;
        __syncthreads();
        int e = cb2 * 1024 + tid;
        if (e < NE) atomicAdd(&hc[eid[e]], 1);
        __syncthreads();
        if (tid < NTE) d_blkcnt[cb2 * NTE + tid] = hc[tid];
    }
}

// ---------------- launch 1: scatter (blocks 0..97) | init gather (rest) ----
__global__ void __launch_bounds__(1024) k_scatter_init(
    const int* __restrict__ eid, const int* __restrict__ src,
    const int* __restrict__ dst, const int* __restrict__ node_ids) {
    int b = blockIdx.x;
    if (b < CNT_BLKS) {
        __shared__ int hc[NTE];
        __shared__ int hbase[NTE];
        __shared__ int htot[NTE];
        if (threadIdx.x < NTE) hc[threadIdx.x] = 0;
        __syncthreads();
        int e = b * 1024 + threadIdx.x;
        int t = 0, loc = 0;
        bool valid = (e < NE);
        if (valid) {
            t = eid[e];
            loc = atomicAdd(&hc[t], 1);
        }
        __syncthreads();
        if (threadIdx.x < NTE) {
            int tt = threadIdx.x, before = 0, total = 0;
            for (int bb = 0; bb < CNT_BLKS; bb++) {
                int c = d_blkcnt[bb * NTE + tt];
                total += c;
                if (bb < b) before += c;
            }
            hbase[tt] = before;
            htot[tt] = total;
        }
        __syncthreads();
        if (threadIdx.x == 0) {
            int run = 0;
            for (int tt = 0; tt < NTE; tt++) {
                hbase[tt] += run;
                run += htot[tt];
            }
        }
        __syncthreads();
        if (valid) {
            int p = hbase[t] + loc;
            d_ssrc[p] = src[e];
            d_sdst[p] = dst[e];
            d_stype[p] = t;
        }
    } else {
        int idx = (b - CNT_BLKS) * 1024 + threadIdx.x;
        if (idx < NN * H) {
            int n = idx >> 5, o = idx & 31;
            d_h[idx] = d_htab[node_ids[n] * H + o];
            d_agg[idx] = 0.0f;
        }
    }
}

// ---------------- launch 2 (even): message kernel --------------------------
#define MSG_TPB 256
#define MSG_WPB (MSG_TPB / 32)
#define MSG_NCH (NE / 32)
#define MSG_BLOCKS ((MSG_NCH + MSG_WPB - 1) / MSG_WPB)

__global__ void __launch_bounds__(MSG_TPB) k_message() {
    __shared__ __align__(16) float hs[MSG_WPB][32][32];
    int wid = threadIdx.x >> 5;
    int lane = threadIdx.x & 31;
    int gw = blockIdx.x * MSG_WPB + wid;
    if (gw >= MSG_NCH) return;

    int e = gw * 32 + lane;
    int sI = __ldg(&d_ssrc[e]);
    int dI = __ldg(&d_sdst[e]);
    int tI = __ldg(&d_stype[e]);

    unsigned sbase = smem_u32(&hs[wid][0][lane]);
#pragma unroll
    for (int j = 0; j < 32; j++) {
        int sj = __shfl_sync(FULLM, sI, j);
        const float* gp = &d_h[sj * H + lane];
        asm volatile("cp.async.ca.shared.global [%0], [%1], 4;"
                     :: "r"(sbase + j * 32 * 4), "l"(gp));
    }
    asm volatile("cp.async.commit_group;");

    int cur_t = __shfl_sync(FULLM, tI, 0);
    unsigned long long w2[H / 2];
    {
        const float* Wt = d_Wtab + cur_t * (H * H);
#pragma unroll
        for (int q = 0; q < H / 2; q++)
            w2[q] = pk(Wt[(2 * q) * H + lane], Wt[(2 * q + 1) * H + lane]);
    }
    asm volatile("cp.async.wait_group 0;");
    __syncwarp();

#pragma unroll 2
    for (int j = 0; j < 32; j++) {
        int tj = __shfl_sync(FULLM, tI, j);
        if (tj != cur_t) {
            cur_t = tj;
            const float* Wt = d_Wtab + cur_t * (H * H);
#pragma unroll
            for (int q = 0; q < H / 2; q++)
                w2[q] = pk(Wt[(2 * q) * H + lane], Wt[(2 * q + 1) * H + lane]);
        }
        const ulonglong2* hp = (const ulonglong2*)hs[wid][j];
        unsigned long long acc = 0;
#pragma unroll
        for (int p = 0; p < 8; p++) {
            ulonglong2 hh = hp[p];
            ffma2(acc, hh.x, w2[2 * p]);
            ffma2(acc, hh.y, w2[2 * p + 1]);
        }
        float2 f = upk(acc);
        int dj = __shfl_sync(FULLM, dI, j);
        atomicAdd(&d_agg[dj * H + lane], f.x + f.y);
    }
}

// ---------------- launch 3 (PROFILED): GRU v3 -------------------------------
// 4 threads/node, 8 outputs each. Inputs and weights in smem with XOR chunk
// swizzle (inputs by ln&7, weights by output-quarter q) -> all hot-loop
// LDS.128 are conflict-free broadcasts. 64 nodes/block, grid 782.
#define G3_TPB 256
#define G3_NPB 64
#define G3_BLOCKS ((NN + G3_NPB - 1) / G3_NPB)  // 782

__global__ void __launch_bounds__(G3_TPB) k_gru3(
    const float* __restrict__ gWih, const float* __restrict__ gWhh,
    const float* __restrict__ gbih, const float* __restrict__ gbhh,
    const float* __restrict__ cb, float* __restrict__ outp) {
    __shared__ __align__(16) float sWih[3 * H * H];
    __shared__ __align__(16) float sWhh[3 * H * H];
    __shared__ __align__(16) float sm_m[G3_NPB * H];
    __shared__ __align__(16) float sm_h[G3_NPB * H];
    __shared__ float sbih[3 * H], sbhh[3 * H];

    int tid = threadIdx.x;
    int nbase = blockIdx.x * G3_NPB;

    // stage weights, swizzled: physical chunk = p ^ ((row>>3)&3)
    {
        const float4* a4 = (const float4*)gWih;
        const float4* b4 = (const float4*)gWhh;
        float4* sa = (float4*)sWih;
        float4* sb = (float4*)sWhh;
#pragma unroll
        for (int i = tid; i < 768; i += G3_TPB) {
            int row = i >> 3, p = i & 7;
            int pp = p ^ ((row >> 3) & 3);
            sa[row * 8 + pp] = __ldg(a4 + i);
            sb[row * 8 + pp] = __ldg(b4 + i);
        }
    }
    if (tid < 3 * H) {
        sbih[tid] = __ldg(gbih + tid);
        sbhh[tid] = __ldg(gbhh + tid);
    }

    // stage inputs, swizzled: physical chunk = p ^ (ln&7).
    // m = relu(agg + cb); also zero agg for the next step.
    {
        float4* smm = (float4*)sm_m;
        float4* smh = (float4*)sm_h;
        float4 z4 = make_float4(0.f, 0.f, 0.f, 0.f);
#pragma unroll
        for (int j = tid; j < G3_NPB * 8; j += G3_TPB) {
            int ln = j >> 3, p = j & 7;
            int n = nbase + ln;
            float4 a = z4, hh = z4;
            if (n < NN) {
                float4 cbv = __ldg((const float4*)cb + p);
                float4* ap = (float4*)(d_agg + (size_t)n * H + p * 4);
                float4 a0 = *ap;
                a.x = fmaxf(a0.x + cbv.x, 0.f);
                a.y = fmaxf(a0.y + cbv.y, 0.f);
                a.z = fmaxf(a0.z + cbv.z, 0.f);
                a.w = fmaxf(a0.w + cbv.w, 0.f);
                *ap = z4;
                hh = *(const float4*)(d_h + (size_t)n * H + p * 4);
            }
            int pp = p ^ (ln & 7);
            smm[ln * 8 + pp] = a;
            smh[ln * 8 + pp] = hh;
        }
    }
    __syncthreads();

    int ln = tid >> 2;
    int q = tid & 3;
    int n = nbase + ln;
    if (n >= NN) return;
    int swn = ln & 7;
    const ulonglong2* mrow = (const ulonglong2*)(sm_m + ln * H);
    const ulonglong2* hrow = (const ulonglong2*)(sm_h + ln * H);

    float hout[8];
#pragma unroll
    for (int oi = 0; oi < 8; oi++) {
        int o = q * 8 + oi;
        const ulonglong2* Wr = (const ulonglong2*)(sWih + o * H);
        const ulonglong2* Wz = (const ulonglong2*)(sWih + (H + o) * H);
        const ulonglong2* Wn = (const ulonglong2*)(sWih + (2 * H + o) * H);
        const ulonglong2* Vr = (const ulonglong2*)(sWhh + o * H);
        const ulonglong2* Vz = (const ulonglong2*)(sWhh + (H + o) * H);
        const ulonglong2* Vn = (const ulonglong2*)(sWhh + (2 * H + o) * H);
        unsigned long long air = pk(sbih[o], 0.f);
        unsigned long long aiz = pk(sbih[H + o], 0.f);
        unsigned long long ain = pk(sbih[2 * H + o], 0.f);
        unsigned long long ahr = pk(sbhh[o], 0.f);
        unsigned long long ahz = pk(sbhh[H + o], 0.f);
        unsigned long long ahn = pk(sbhh[2 * H + o], 0.f);
#pragma unroll
        for (int p = 0; p < 8; p++) {
            int pi = p ^ swn;   // physical chunk for inputs (logical p)
            int pw = p ^ q;     // physical chunk for weights (logical p)
            ulonglong2 mv = mrow[pi];
            ulonglong2 hv = hrow[pi];
            ulonglong2 w;
            w = Wr[pw]; ffma2(air, mv.x, w.x); ffma2(air, mv.y, w.y);
            w = Wz[pw]; ffma2(aiz, mv.x, w.x); ffma2(aiz, mv.y, w.y);
            w = Wn[pw]; ffma2(ain, mv.x, w.x); ffma2(ain, mv.y, w.y);
            w = Vr[pw]; ffma2(ahr, hv.x, w.x); ffma2(ahr, hv.y, w.y);
            w = Vz[pw]; ffma2(ahz, hv.x, w.x); ffma2(ahz, hv.y, w.y);
            w = Vn[pw]; ffma2(ahn, hv.x, w.x); ffma2(ahn, hv.y, w.y);
        }
        float2 f, g;
        f = upk(air); g = upk(ahr);
        float r = sigm((f.x + f.y) + (g.x + g.y));
        f = upk(aiz); g = upk(ahz);
        float z = sigm((f.x + f.y) + (g.x + g.y));
        f = upk(ain); g = upk(ahn);
        float nv = tanh_fast((f.x + f.y) + r * (g.x + g.y));
        int ch = o >> 2;
        float hold = sm_h[ln * H + ((ch ^ swn) << 2) + (o & 3)];
        hout[oi] = (1.0f - z) * nv + z * hold;
    }

    float4* hp = (float4*)(d_h + (size_t)n * H + q * 8);
    float4 v0 = make_float4(hout[0], hout[1], hout[2], hout[3]);
    float4 v1 = make_float4(hout[4], hout[5], hout[6], hout[7]);
    hp[0] = v0;
    hp[1] = v1;
    if (outp) {
        float4* op = (float4*)(outp + (size_t)n * H + q * 8);
        op[0] = v0;
        op[1] = v1;
    }
}

// ---------------- launch ----------------
extern "C" void kernel_launch(void* const* d_in, const int* in_sizes, int n_in,
                              void* d_out, int out_size) {
    const int* node_ids = (const int*)d_in[0];
    const int* edge_ids = (const int*)d_in[1];
    const int* src = (const int*)d_in[2];
    const int* dst = (const int*)d_in[3];
    const float* node_emb = (const float*)d_in[4];
    const float* edge_emb = (const float*)d_in[5];
    const float* proj_W = (const float*)d_in[6];
    const float* proj_b = (const float*)d_in[7];
    const float* eW1 = (const float*)d_in[8];
    const float* eb1 = (const float*)d_in[9];
    const float* eW2 = (const float*)d_in[10];
    const float* eb2 = (const float*)d_in[11];
    const float* conv_bias = (const float*)d_in[12];
    const float* gWih = (const float*)d_in[13];
    const float* gWhh = (const float*)d_in[14];
    const float* gbih = (const float*)d_in[15];
    const float* gbhh = (const float*)d_in[16];
    float* out = (float*)d_out;

    k_setupA<<<SETUPA_BLKS, 1024>>>(edge_emb, eW1, eb1, eW2, eb2,
                                    node_emb, proj_W, proj_b, edge_ids);   // 0
    k_scatter_init<<<CNT_BLKS + INIT_BLKS, 1024>>>(edge_ids, src, dst,
                                                   node_ids);              // 1

    for (int s = 0; s < STEPS; s++) {
        k_message<<<MSG_BLOCKS, MSG_TPB>>>();                              // 2, 4, ...
        float* op = (s == STEPS - 1) ? out : nullptr;
        k_gru3<<<G3_BLOCKS, G3_TPB>>>(gWih, gWhh, gbih, gbhh,              // 3 (profiled)
                                      conv_bias, op);
    }
}

// round 10
// speedup vs baseline: 2.0483x; 1.2784x over previous
#include <cuda_runtime.h>

#define NN 50000
#define NE 100000
#define NODE_IN 64
#define EDGE_IN 16
#define H 32
#define EH 128
#define NTN 343
#define NTE 21
#define STEPS 6
#define FULLM 0xffffffffu

#define CNT_BLKS ((NE + 1023) / 1024)             // 98
#define HT_BLKS ((NTN * H + 1023) / 1024)         // 11
#define SETUPA_BLKS (NTE + HT_BLKS + CNT_BLKS)
#define INIT_BLKS ((NN * H + 1023) / 1024)        // 1563

// ---------------- device scratch ----------------
__device__ float d_h[NN * H];
__device__ float d_agg[NN * H];
__device__ float d_Wtab[NTE * H * H];
__device__ float d_htab[NTN * H];
__device__ int d_ssrc[NE];
__device__ int d_sdst[NE];
__device__ int d_stype[NE];
__device__ int d_blkcnt[CNT_BLKS * NTE];

// ---------------- helpers ----------------
__device__ __forceinline__ unsigned long long pk(float a, float b) {
    unsigned long long r;
    asm("mov.b64 %0, {%1, %2};" : "=l"(r) : "f"(a), "f"(b));
    return r;
}
__device__ __forceinline__ float2 upk(unsigned long long v) {
    float2 f;
    asm("mov.b64 {%0, %1}, %2;" : "=f"(f.x), "=f"(f.y) : "l"(v));
    return f;
}
__device__ __forceinline__ void ffma2(unsigned long long& acc,
                                      unsigned long long a,
                                      unsigned long long b) {
    asm("fma.rn.f32x2 %0, %1, %2, %0;" : "+l"(acc) : "l"(a), "l"(b));
}
__device__ __forceinline__ float sigm(float x) {
    return 1.0f / (1.0f + __expf(-x));
}
__device__ __forceinline__ float tanh_fast(float x) {
    float e = __expf(2.0f * x);
    return 1.0f - 2.0f / (e + 1.0f);
}
__device__ __forceinline__ unsigned smem_u32(const void* p) {
    unsigned a;
    asm("{ .reg .u64 t; cvta.to.shared.u64 t, %1; cvt.u32.u64 %0, t; }"
        : "=r"(a) : "l"(p));
    return a;
}

// ---------------- launch 0: setup A (wtab | htab | count) ------------------
__global__ void __launch_bounds__(1024) k_setupA(
    const float* __restrict__ edge_emb, const float* __restrict__ eW1,
    const float* __restrict__ eb1, const float* __restrict__ eW2,
    const float* __restrict__ eb2, const float* __restrict__ node_emb,
    const float* __restrict__ proj_W, const float* __restrict__ proj_b,
    const int* __restrict__ eid) {
    int tid = threadIdx.x;
    int b = blockIdx.x;
    if (b < NTE) {
        __shared__ float sh[EH];
        if (tid < EH) {
            float a = eb1[tid];
#pragma unroll
            for (int i = 0; i < EDGE_IN; i++)
                a = fmaf(edge_emb[b * EDGE_IN + i], eW1[i * EH + tid], a);
            sh[tid] = fmaxf(a, 0.0f);
        }
        __syncthreads();
        float acc = eb2[tid];
#pragma unroll 8
        for (int i = 0; i < EH; i++)
            acc = fmaf(sh[i], eW2[i * (H * H) + tid], acc);
        d_Wtab[b * (H * H) + tid] = acc;
    } else if (b < NTE + HT_BLKS) {
        int idx = (b - NTE) * 1024 + tid;
        if (idx < NTN * H) {
            int r = idx >> 5, o = idx & 31;
            float acc = proj_b[o];
#pragma unroll 8
            for (int i = 0; i < NODE_IN; i++)
                acc = fmaf(node_emb[r * NODE_IN + i], proj_W[i * H + o], acc);
            d_htab[idx] = fmaxf(acc, 0.0f);
        }
    } else {
        __shared__ int hc[NTE];
        int cb2 = b - NTE - HT_BLKS;
        if (tid < NTE) hc[tid] = 0;
        __syncthreads();
        int e = cb2 * 1024 + tid;
        if (e < NE) atomicAdd(&hc[eid[e]], 1);
        __syncthreads();
        if (tid < NTE) d_blkcnt[cb2 * NTE + tid] = hc[tid];
    }
}

// ---------------- launch 1: scatter (blocks 0..97) | init gather (rest) ----
__global__ void __launch_bounds__(1024) k_scatter_init(
    const int* __restrict__ eid, const int* __restrict__ src,
    const int* __restrict__ dst, const int* __restrict__ node_ids) {
    int b = blockIdx.x;
    if (b < CNT_BLKS) {
        __shared__ int hc[NTE];
        __shared__ int hbase[NTE];
        __shared__ int htot[NTE];
        if (threadIdx.x < NTE) hc[threadIdx.x] = 0;
        __syncthreads();
        int e = b * 1024 + threadIdx.x;
        int t = 0, loc = 0;
        bool valid = (e < NE);
        if (valid) {
            t = eid[e];
            loc = atomicAdd(&hc[t], 1);
        }
        __syncthreads();
        if (threadIdx.x < NTE) {
            int tt = threadIdx.x, before = 0, total = 0;
            for (int bb = 0; bb < CNT_BLKS; bb++) {
                int c = d_blkcnt[bb * NTE + tt];
                total += c;
                if (bb < b) before += c;
            }
            hbase[tt] = before;
            htot[tt] = total;
        }
        __syncthreads();
        if (threadIdx.x == 0) {
            int run = 0;
            for (int tt = 0; tt < NTE; tt++) {
                hbase[tt] += run;
                run += htot[tt];
            }
        }
        __syncthreads();
        if (valid) {
            int p = hbase[t] + loc;
            d_ssrc[p] = src[e];
            d_sdst[p] = dst[e];
            d_stype[p] = t;
        }
    } else {
        int idx = (b - CNT_BLKS) * 1024 + threadIdx.x;
        if (idx < NN * H) {
            int n = idx >> 5, o = idx & 31;
            d_h[idx] = d_htab[node_ids[n] * H + o];
            d_agg[idx] = 0.0f;
        }
    }
}

// ---------------- launch 2 (even): message kernel --------------------------
#define MSG_TPB 256
#define MSG_WPB (MSG_TPB / 32)
#define MSG_NCH (NE / 32)
#define MSG_BLOCKS ((MSG_NCH + MSG_WPB - 1) / MSG_WPB)

__global__ void __launch_bounds__(MSG_TPB) k_message() {
    __shared__ __align__(16) float hs[MSG_WPB][32][32];
    int wid = threadIdx.x >> 5;
    int lane = threadIdx.x & 31;
    int gw = blockIdx.x * MSG_WPB + wid;
    if (gw >= MSG_NCH) return;

    int e = gw * 32 + lane;
    int sI = __ldg(&d_ssrc[e]);
    int dI = __ldg(&d_sdst[e]);
    int tI = __ldg(&d_stype[e]);

    unsigned sbase = smem_u32(&hs[wid][0][lane]);
#pragma unroll
    for (int j = 0; j < 32; j++) {
        int sj = __shfl_sync(FULLM, sI, j);
        const float* gp = &d_h[sj * H + lane];
        asm volatile("cp.async.ca.shared.global [%0], [%1], 4;"
                     :: "r"(sbase + j * 32 * 4), "l"(gp));
    }
    asm volatile("cp.async.commit_group;");

    int cur_t = __shfl_sync(FULLM, tI, 0);
    unsigned long long w2[H / 2];
    {
        const float* Wt = d_Wtab + cur_t * (H * H);
#pragma unroll
        for (int q = 0; q < H / 2; q++)
            w2[q] = pk(Wt[(2 * q) * H + lane], Wt[(2 * q + 1) * H + lane]);
    }
    asm volatile("cp.async.wait_group 0;");
    __syncwarp();

#pragma unroll 2
    for (int j = 0; j < 32; j++) {
        int tj = __shfl_sync(FULLM, tI, j);
        if (tj != cur_t) {
            cur_t = tj;
            const float* Wt = d_Wtab + cur_t * (H * H);
#pragma unroll
            for (int q = 0; q < H / 2; q++)
                w2[q] = pk(Wt[(2 * q) * H + lane], Wt[(2 * q + 1) * H + lane]);
        }
        const ulonglong2* hp = (const ulonglong2*)hs[wid][j];
        unsigned long long acc = 0;
#pragma unroll
        for (int p = 0; p < 8; p++) {
            ulonglong2 hh = hp[p];
            ffma2(acc, hh.x, w2[2 * p]);
            ffma2(acc, hh.y, w2[2 * p + 1]);
        }
        float2 f = upk(acc);
        int dj = __shfl_sync(FULLM, dI, j);
        atomicAdd(&d_agg[dj * H + lane], f.x + f.y);
    }
}

// ---------------- launch 3 (PROFILED): GRU v4 -------------------------------
// 2 threads/node, split by GEMM side: half0 = m@Wih (m in regs),
// half1 = h@Whh (h in regs). Per iteration: output pair (o0,o1), 6 dots/lane,
// 3 shfl_xor cross the pair, each lane finalizes ONE output. Weights in smem
// padded (row stride 68 floats, halves +36) -> conflict-free 2-addr LDS.128.
#define G4_TPB 256
#define G4_NPB (G4_TPB / 2)                        // 128 nodes/block
#define G4_BLOCKS ((NN + G4_NPB - 1) / G4_NPB)     // 391
#define WROW 68

__global__ void __launch_bounds__(G4_TPB, 3) k_gru4(
    const float* __restrict__ gWih, const float* __restrict__ gWhh,
    const float* __restrict__ gbih, const float* __restrict__ gbhh,
    const float* __restrict__ cb, float* __restrict__ outp) {
    __shared__ __align__(16) float sW[96 * WROW];  // row r: [Wih_r | pad | Whh_r]
    __shared__ float sb[192];
    __shared__ __align__(16) float scb[32];

    int tid = threadIdx.x;
    for (int i = tid; i < 96 * 32; i += G4_TPB) {
        int r = i >> 5, c = i & 31;
        sW[r * WROW + c] = __ldg(gWih + i);
        sW[r * WROW + 36 + c] = __ldg(gWhh + i);
    }
    if (tid < 192)
        sb[tid] = (tid < 96) ? __ldg(gbih + tid) : __ldg(gbhh + tid - 96);
    if (tid < 32) scb[tid] = __ldg(cb + tid);
    __syncthreads();

    int nr = blockIdx.x * G4_NPB + (tid >> 1);
    int half = tid & 1;
    bool valid = (nr < NN);
    int n = valid ? nr : (NN - 1);  // clamp; stores predicated (keeps warp full for shfl)

    // hoist my side's input vector into 16 packed regs
    unsigned long long x2[16];
    if (half == 0) {
        float4* ap = (float4*)(d_agg + (size_t)n * H);
        const float4* cb4 = (const float4*)scb;
        float4 z4 = make_float4(0.f, 0.f, 0.f, 0.f);
#pragma unroll
        for (int p = 0; p < 8; p++) {
            float4 a = ap[p];
            float4 c = cb4[p];
            float m0 = fmaxf(a.x + c.x, 0.f);
            float m1 = fmaxf(a.y + c.y, 0.f);
            float m2v = fmaxf(a.z + c.z, 0.f);
            float m3 = fmaxf(a.w + c.w, 0.f);
            x2[2 * p] = pk(m0, m1);
            x2[2 * p + 1] = pk(m2v, m3);
            if (valid) ap[p] = z4;  // reset agg for next step
        }
    } else {
        const float4* hp = (const float4*)(d_h + (size_t)n * H);
#pragma unroll
        for (int p = 0; p < 8; p++) {
            float4 v = hp[p];
            x2[2 * p] = pk(v.x, v.y);
            x2[2 * p + 1] = pk(v.z, v.w);
        }
    }

    const float* wbase = sW + half * 36;
    const float* bbase = sb + half * 96;
    float* hrow = d_h + (size_t)n * H;
    float* orow = outp + (size_t)n * H;

#pragma unroll 4
    for (int oo = 0; oo < 16; oo++) {
        int o0 = 2 * oo, o1 = o0 + 1;
        const ulonglong2* R0 = (const ulonglong2*)(wbase + o0 * WROW);
        const ulonglong2* R1 = (const ulonglong2*)(wbase + o1 * WROW);
        const ulonglong2* Z0 = (const ulonglong2*)(wbase + (32 + o0) * WROW);
        const ulonglong2* Z1 = (const ulonglong2*)(wbase + (32 + o1) * WROW);
        const ulonglong2* N0 = (const ulonglong2*)(wbase + (64 + o0) * WROW);
        const ulonglong2* N1 = (const ulonglong2*)(wbase + (64 + o1) * WROW);
        unsigned long long ar0 = pk(bbase[o0], 0.f);
        unsigned long long ar1 = pk(bbase[o1], 0.f);
        unsigned long long az0 = pk(bbase[32 + o0], 0.f);
        unsigned long long az1 = pk(bbase[32 + o1], 0.f);
        unsigned long long an0 = pk(bbase[64 + o0], 0.f);
        unsigned long long an1 = pk(bbase[64 + o1], 0.f);
#pragma unroll
        for (int p = 0; p < 8; p++) {
            unsigned long long xa = x2[2 * p], xb = x2[2 * p + 1];
            ulonglong2 w;
            w = R0[p]; ffma2(ar0, xa, w.x); ffma2(ar0, xb, w.y);
            w = R1[p]; ffma2(ar1, xa, w.x); ffma2(ar1, xb, w.y);
            w = Z0[p]; ffma2(az0, xa, w.x); ffma2(az0, xb, w.y);
            w = Z1[p]; ffma2(az1, xa, w.x); ffma2(az1, xb, w.y);
            w = N0[p]; ffma2(an0, xa, w.x); ffma2(an0, xb, w.y);
            w = N1[p]; ffma2(an1, xa, w.x); ffma2(an1, xb, w.y);
        }
        float2 f;
        f = upk(ar0); float sr0 = f.x + f.y;
        f = upk(ar1); float sr1 = f.x + f.y;
        f = upk(az0); float sz0 = f.x + f.y;
        f = upk(az1); float sz1 = f.x + f.y;
        f = upk(an0); float sn0 = f.x + f.y;
        f = upk(an1); float sn1 = f.x + f.y;

        // cross the pair: lane finalizes o_self = o0 + half
        float er = __shfl_xor_sync(FULLM, half ? sr0 : sr1, 1);
        float ez = __shfl_xor_sync(FULLM, half ? sz0 : sz1, 1);
        float en = __shfl_xor_sync(FULLM, half ? sn0 : sn1, 1);
        float lr = half ? sr1 : sr0;
        float lz = half ? sz1 : sz0;
        float r = sigm(lr + er);
        float z = sigm(lz + ez);
        float i_n = half ? en : sn0;
        float h_n = half ? sn1 : en;
        float nv = tanh_fast(i_n + r * h_n);
        int o_self = o0 + half;
        float hold = hrow[o_self];  // L1 hit (read-before-own-write)
        float hnew = (1.0f - z) * nv + z * hold;
        if (valid) {
            hrow[o_self] = hnew;
            if (outp) orow[o_self] = hnew;
        }
    }
}

// ---------------- launch ----------------
extern "C" void kernel_launch(void* const* d_in, const int* in_sizes, int n_in,
                              void* d_out, int out_size) {
    const int* node_ids = (const int*)d_in[0];
    const int* edge_ids = (const int*)d_in[1];
    const int* src = (const int*)d_in[2];
    const int* dst = (const int*)d_in[3];
    const float* node_emb = (const float*)d_in[4];
    const float* edge_emb = (const float*)d_in[5];
    const float* proj_W = (const float*)d_in[6];
    const float* proj_b = (const float*)d_in[7];
    const float* eW1 = (const float*)d_in[8];
    const float* eb1 = (const float*)d_in[9];
    const float* eW2 = (const float*)d_in[10];
    const float* eb2 = (const float*)d_in[11];
    const float* conv_bias = (const float*)d_in[12];
    const float* gWih = (const float*)d_in[13];
    const float* gWhh = (const float*)d_in[14];
    const float* gbih = (const float*)d_in[15];
    const float* gbhh = (const float*)d_in[16];
    float* out = (float*)d_out;

    k_setupA<<<SETUPA_BLKS, 1024>>>(edge_emb, eW1, eb1, eW2, eb2,
                                    node_emb, proj_W, proj_b, edge_ids);   // 0
    k_scatter_init<<<CNT_BLKS + INIT_BLKS, 1024>>>(edge_ids, src, dst,
                                                   node_ids);              // 1

    for (int s = 0; s < STEPS; s++) {
        k_message<<<MSG_BLOCKS, MSG_TPB>>>();                              // 2, 4, ...
        float* op = (s == STEPS - 1) ? out : nullptr;
        k_gru4<<<G4_BLOCKS, G4_TPB>>>(gWih, gWhh, gbih, gbhh,              // 3 (profiled)
                                      conv_bias, op);
    }
}